// round 7
// baseline (speedup 1.0000x reference)
#include <cuda_runtime.h>
#include <cstdint>

// Problem constants
#define B_   1024
#define T_   512
#define I_   16
#define H_   50
#define G_   200      // 4*H
#define FCD  64
#define NB   7        // rows per block -> grid 147, single wave
#define NTH  672      // 21 warps: 3 groups x 7 warps (200 gate threads each)
#define NC1  (NB * H_)        // 350
#define NCELL (2 * NB * H_)   // 700
#define SLAB (NB * G_)        // 1400 floats of gx per block per step
#define SLAB_BYTES (SLAB * 4) // 5600

typedef unsigned long long ull;

// Precomputed bias-folded x-gates for layer 1: [t][b][g]. Padding covers the
// boundary block's over-read (rows 1024..1028, finite garbage, unused).
__device__ float g_gx[(size_t)T_ * B_ * G_ + 2048];

// ---- f32x2 packed helpers (sm_103a FFMA2) ----
__device__ __forceinline__ void fma2(ull& acc, ull a, ull b) {
    asm("fma.rn.f32x2 %0, %1, %2, %0;" : "+l"(acc) : "l"(a), "l"(b));
}
__device__ __forceinline__ ull pk2(float x, float y) {
    ull r;
    asm("mov.b64 %0, {%1, %2};" : "=l"(r) : "f"(x), "f"(y));
    return r;
}
__device__ __forceinline__ float rsum(ull v) {
    float2 r;
    asm("mov.b64 {%0, %1}, %2;" : "=f"(r.x), "=f"(r.y) : "l"(v));
    return r.x + r.y;
}

// ---- fast activations: single-MUFU ex2 / rcp ----
__device__ __forceinline__ float fex2(float x) {
    float r;
    asm("ex2.approx.f32 %0, %1;" : "=f"(r) : "f"(x));
    return r;
}
__device__ __forceinline__ float frcp(float x) {
    float r;
    asm("rcp.approx.f32 %0, %1;" : "=f"(r) : "f"(x));
    return r;
}
#define LOG2E  1.4426950408889634f
__device__ __forceinline__ float sigf(float x) {
    return frcp(1.0f + fex2(-LOG2E * x));
}
__device__ __forceinline__ float tanh_f(float x) {
    return 2.0f * frcp(1.0f + fex2(-2.0f * LOG2E * x)) - 1.0f;
}

__device__ __forceinline__ uint32_t s2u(const void* p) {
    uint32_t a;
    asm("{ .reg .u64 t; cvta.to.shared.u64 t, %1; cvt.u32.u64 %0, t; }"
        : "=r"(a) : "l"(p));
    return a;
}
#define MBINIT(a, c) \
    asm volatile("mbarrier.init.shared.b64 [%0], %1;" :: "r"(a), "r"(c) : "memory")
#define MBEXPECT(a, n) \
    asm volatile("mbarrier.arrive.expect_tx.shared.b64 _, [%0], %1;" :: "r"(a), "r"(n) : "memory")
#define BULKCP(dst, src, n, mb) \
    asm volatile("cp.async.bulk.shared::cta.global.mbarrier::complete_tx::bytes [%0], [%1], %2, [%3];" \
                 :: "r"(dst), "l"(src), "r"(n), "r"(mb) : "memory")
__device__ __forceinline__ void mbwait(uint32_t mb, uint32_t parity) {
    uint32_t done;
    asm volatile(
        "{\n\t.reg .pred p;\n\t"
        "mbarrier.try_wait.parity.acquire.cta.shared::cta.b64 p, [%1], %2;\n\t"
        "selp.b32 %0, 1, 0, p;\n\t}"
        : "=r"(done) : "r"(mb), "r"(parity) : "memory");
    if (!done) {
        asm volatile(
            "{\n\t.reg .pred P1;\n\t"
            "W_%=:\n\t"
            "mbarrier.try_wait.parity.acquire.cta.shared::cta.b64 P1, [%0], %1, 0x989680;\n\t"
            "@P1 bra.uni D_%=;\n\t"
            "bra.uni W_%=;\n\t"
            "D_%=:\n\t}"
            :: "r"(mb), "r"(parity) : "memory");
    }
}

// ============================================================================
// Kernel 1: gx[t][b][g] = b_ih0[g] + b_hh0[g] + x[b,t,:] . w_ih0[g,:]
// ============================================================================
#define TT 128
__global__ __launch_bounds__(256, 4)
void xgate_kernel(const float* __restrict__ x,
                  const float* __restrict__ w_ih0,
                  const float* __restrict__ b_ih0,
                  const float* __restrict__ b_hh0) {
    __shared__ __align__(16) float xs[TT][I_];   // 8 KB
    const int b   = blockIdx.y;
    const int t0  = blockIdx.x * TT;
    const int tid = threadIdx.x;

    const float4* src = (const float4*)(x + ((size_t)b * T_ + t0) * I_);
    ((float4*)xs)[tid]       = src[tid];
    ((float4*)xs)[tid + 256] = src[tid + 256];
    __syncthreads();

    if (tid < G_) {
        ull w[8];
        #pragma unroll
        for (int k2 = 0; k2 < 8; k2++)
            w[k2] = pk2(__ldg(&w_ih0[tid * I_ + 2 * k2]),
                        __ldg(&w_ih0[tid * I_ + 2 * k2 + 1]));
        const float bias = __ldg(&b_ih0[tid]) + __ldg(&b_hh0[tid]);
        for (int tt = 0; tt < TT; tt++) {
            ull acc = pk2(bias, 0.0f);
            #pragma unroll
            for (int q = 0; q < 4; q++) {
                const ulonglong2 v = *(const ulonglong2*)&xs[tt][4 * q];
                fma2(acc, w[2 * q],     v.x);
                fma2(acc, w[2 * q + 1], v.y);
            }
            g_gx[((size_t)(t0 + tt) * B_ + b) * G_ + tid] = rsum(acc);
        }
    }
}

// ============================================================================
// Kernel 2: fused 2-layer LSTM recurrence + FC head.
// iter it: L1 step it (gx[it], h1_{it-1});  L2 step it-1 (h1_{it-1}, h2_{it-2})
// 3 gate groups of 7 warps: G0: gx + h1.Whh0 ; G1: h1.Wih1 ; G2: h2.Whh1.
// Gate loop: per row, batch ALL 13 LDS.128 up front (MLP=13 hides lat 29),
// then two independent 13-deep FFMA2 chains. Store per row.
// ============================================================================
__global__ __launch_bounds__(NTH, 1)
void fused_lstm_kernel(const float* __restrict__ w_hh0,  // [G, H]
                       const float* __restrict__ w_ih1,  // [G, H]
                       const float* __restrict__ w_hh1,  // [G, H]
                       const float* __restrict__ b_ih1,
                       const float* __restrict__ b_hh1,
                       const float* __restrict__ fc1_w,  // [FC, H]
                       const float* __restrict__ fc1_b,
                       const float* __restrict__ fc2_w,  // [1, FC]
                       const float* __restrict__ fc2_b,
                       float* __restrict__ out)          // [B, 1]
{
    __shared__ __align__(16) float hx[2][NB][52];   // [0]=h1, [1]=h2 (padded)
    __shared__ __align__(16) float gxs[2][SLAB];    // gx slab double buffer
    __shared__ float gl1[NB][G_];                   // L1 gates (full)
    __shared__ float p1[NB][G_];                    // L2 partial (h1 part)
    __shared__ float p2[NB][G_];                    // L2 partial (h2 part)
    __shared__ __align__(8) ull mbar[2];

    const int tid  = threadIdx.x;
    const int row0 = blockIdx.x * NB;
    const int gidx = tid / 224;            // group 0/1/2
    const int g    = tid - gidx * 224;     // gate index if < 200
    const bool isG = (g < G_);

    const uint32_t mb0 = s2u(&mbar[0]);
    const uint32_t mb1 = s2u(&mbar[1]);
    const uint32_t gx0 = s2u(&gxs[0][0]);
    const uint32_t gx1 = s2u(&gxs[1][0]);

    for (int i = tid; i < 2 * NB * 52; i += NTH) ((float*)hx)[i] = 0.0f;
    if (tid == 0) { MBINIT(mb0, 1); MBINIT(mb1, 1); }
    __syncthreads();

    if (tid == 0) {
        MBEXPECT(mb0, SLAB_BYTES);
        BULKCP(gx0, (const void*)(g_gx + (size_t)row0 * G_), SLAB_BYTES, mb0);
    }

    // ---- weights: one matrix per group, 26 f32x2 chunks each ----
    ull w[26];
    float bias2 = 0.0f;
    if (isG) {
        const float* wm = (gidx == 0) ? w_hh0 : (gidx == 1) ? w_ih1 : w_hh1;
        #pragma unroll
        for (int k2 = 0; k2 < 26; k2++) {
            float a0 = (2 * k2     < H_) ? __ldg(&wm[g * H_ + 2 * k2])     : 0.0f;
            float a1 = (2 * k2 + 1 < H_) ? __ldg(&wm[g * H_ + 2 * k2 + 1]) : 0.0f;
            w[k2] = pk2(a0, a1);
        }
        if (gidx == 1) bias2 = __ldg(&b_ih1[g]) + __ldg(&b_hh1[g]);
    }

    // ---- combine ownership: cell tid (+ cell tid+672 for tid<28) ----
    float c_st[2] = {0.0f, 0.0f};
    int   coff[2], hoff[2];
    bool  cval[2], cl2[2];
    #pragma unroll
    for (int k = 0; k < 2; k++) {
        const int cell = tid + k * NTH;
        cval[k] = (cell < NCELL);
        const int c = cval[k] ? cell : 0;
        cl2[k] = (c >= NC1);
        const int rem = cl2[k] ? c - NC1 : c;
        const int r = rem / H_;
        const int j = rem - r * H_;
        coff[k] = r * G_ + j;
        hoff[k] = (cl2[k] ? NB * 52 : 0) + r * 52 + j;
    }

    int ph0 = 0, ph1 = 0;
    for (int it = 0; it <= T_; it++) {
        const int buf = it & 1;

        if (tid == 0 && it < T_) {
            const int tn = (it + 1 < T_) ? (it + 1) : (T_ - 1);
            const uint32_t mbn = buf ? mb0 : mb1;
            const uint32_t gxn = buf ? gx0 : gx1;
            MBEXPECT(mbn, SLAB_BYTES);
            BULKCP(gxn, (const void*)(g_gx + ((size_t)tn * B_ + row0) * G_),
                   SLAB_BYTES, mbn);
        }

        // ---- gate phase: row-major, batched loads, dual acc chains ----
        if (isG) {
            const int hsel = (gidx == 2) ? 1 : 0;
            if (gidx == 0) {
                mbwait(buf ? mb1 : mb0, buf ? ph1 : ph0);
                if (buf) ph1 ^= 1; else ph0 ^= 1;
            }
            float* dst = (gidx == 0) ? &gl1[0][0] : (gidx == 1) ? &p1[0][0] : &p2[0][0];
            #pragma unroll
            for (int r = 0; r < NB; r++) {
                ull ae, ao;
                if (gidx == 0)      ae = pk2(gxs[buf][r * G_ + g], 0.0f);
                else if (gidx == 1) ae = pk2(bias2, 0.0f);
                else                ae = 0ull;
                ao = 0ull;
                ulonglong2 v[13];
                #pragma unroll
                for (int q = 0; q < 13; q++)
                    v[q] = *(const ulonglong2*)&hx[hsel][r][4 * q];
                #pragma unroll
                for (int q = 0; q < 13; q++) {
                    fma2(ae, w[2 * q],     v[q].x);
                    fma2(ao, w[2 * q + 1], v[q].y);
                }
                dst[r * G_ + g] = rsum(ae) + rsum(ao);
            }
        }
        __syncthreads();

        // ---- combine: all threads, 1-2 cells each (gate order i, f, g, o) ----
        #pragma unroll
        for (int k = 0; k < 2; k++) {
            if (cval[k]) {
                const bool act = cl2[k] ? (it >= 1) : (it < T_);
                if (act) {
                    const int o = coff[k];
                    float gi, gf, gg, go;
                    if (cl2[k]) {
                        const float* q1 = &p1[0][0];
                        const float* q2 = &p2[0][0];
                        gi = q1[o]           + q2[o];
                        gf = q1[o + H_]      + q2[o + H_];
                        gg = q1[o + 2 * H_]  + q2[o + 2 * H_];
                        go = q1[o + 3 * H_]  + q2[o + 3 * H_];
                    } else {
                        const float* q0 = &gl1[0][0];
                        gi = q0[o];
                        gf = q0[o + H_];
                        gg = q0[o + 2 * H_];
                        go = q0[o + 3 * H_];
                    }
                    const float ig = sigf(gi);
                    const float fg = sigf(gf);
                    const float gv = tanh_f(gg);
                    const float og = sigf(go);
                    c_st[k] = fg * c_st[k] + ig * gv;
                    ((float*)hx)[hoff[k]] = og * tanh_f(c_st[k]);
                }
            }
        }
        __syncthreads();
    }

    // ---- FC head: warps 0-6 each handle one batch row, shfl reduction ----
    const int wid  = tid / 32;
    const int lane = tid - wid * 32;
    if (wid < NB) {
        const int row = row0 + wid;
        if (row < B_) {
            float s = 0.0f;
            #pragma unroll
            for (int uu = 0; uu < 2; uu++) {
                const int u = lane + uu * 32;
                float a = __ldg(&fc1_b[u]);
                #pragma unroll
                for (int k = 0; k < H_; k++)
                    a += __ldg(&fc1_w[u * H_ + k]) * hx[1][wid][k];
                a = fmaxf(a, 0.0f);
                s += a * __ldg(&fc2_w[u]);
            }
            #pragma unroll
            for (int off = 16; off > 0; off >>= 1)
                s += __shfl_down_sync(0xffffffffu, s, off);
            if (lane == 0) out[row] = s + __ldg(&fc2_b[0]);
        }
    }
}

extern "C" void kernel_launch(void* const* d_in, const int* in_sizes, int n_in,
                              void* d_out, int out_size) {
    const float* x     = (const float*)d_in[0];
    const float* w_ih0 = (const float*)d_in[1];
    const float* w_hh0 = (const float*)d_in[2];
    const float* b_ih0 = (const float*)d_in[3];
    const float* b_hh0 = (const float*)d_in[4];
    const float* w_ih1 = (const float*)d_in[5];
    const float* w_hh1 = (const float*)d_in[6];
    const float* b_ih1 = (const float*)d_in[7];
    const float* b_hh1 = (const float*)d_in[8];
    const float* fc1_w = (const float*)d_in[9];
    const float* fc1_b = (const float*)d_in[10];
    const float* fc2_w = (const float*)d_in[11];
    const float* fc2_b = (const float*)d_in[12];
    float* out = (float*)d_out;

    dim3 xg_grid(T_ / TT, B_);
    xgate_kernel<<<xg_grid, 256>>>(x, w_ih0, b_ih0, b_hh0);

    const int grid = (B_ + NB - 1) / NB;   // 147
    fused_lstm_kernel<<<grid, NTH>>>(
        w_hh0, w_ih1, w_hh1, b_ih1, b_hh1,
        fc1_w, fc1_b, fc2_w, fc2_b, out);
}

// round 8
// speedup vs baseline: 1.0475x; 1.0475x over previous
#include <cuda_runtime.h>
#include <cstdint>

// Problem constants
#define B_   1024
#define T_   512
#define I_   16
#define H_   50
#define G_   200      // 4*H
#define FCD  64
#define NB   7        // rows per block -> grid 147, single wave
#define NTH  672      // 21 warps: 3 groups x 7 warps (200 gate threads each)
#define NC1  (NB * H_)        // 350
#define NCELL (2 * NB * H_)   // 700
#define SLAB (NB * G_)        // 1400 floats of gx per block per step
#define SLAB_BYTES (SLAB * 4) // 5600

typedef unsigned long long ull;

// Precomputed bias-folded x-gates for layer 1: [t][b][g]. Padding covers the
// boundary block's over-read (rows 1024..1028, finite garbage, unused).
__device__ float g_gx[(size_t)T_ * B_ * G_ + 2048];

// ---- f32x2 packed helpers (sm_103a FFMA2) ----
__device__ __forceinline__ void fma2(ull& acc, ull a, ull b) {
    asm("fma.rn.f32x2 %0, %1, %2, %0;" : "+l"(acc) : "l"(a), "l"(b));
}
__device__ __forceinline__ ull pk2(float x, float y) {
    ull r;
    asm("mov.b64 %0, {%1, %2};" : "=l"(r) : "f"(x), "f"(y));
    return r;
}
__device__ __forceinline__ float rsum(ull v) {
    float2 r;
    asm("mov.b64 {%0, %1}, %2;" : "=f"(r.x), "=f"(r.y) : "l"(v));
    return r.x + r.y;
}

// ---- fast activations: single-MUFU ex2 / rcp ----
__device__ __forceinline__ float fex2(float x) {
    float r;
    asm("ex2.approx.f32 %0, %1;" : "=f"(r) : "f"(x));
    return r;
}
__device__ __forceinline__ float frcp(float x) {
    float r;
    asm("rcp.approx.f32 %0, %1;" : "=f"(r) : "f"(x));
    return r;
}
#define LOG2E  1.4426950408889634f
__device__ __forceinline__ float sigf(float x) {
    return frcp(1.0f + fex2(-LOG2E * x));
}
__device__ __forceinline__ float tanh_f(float x) {
    return 2.0f * frcp(1.0f + fex2(-2.0f * LOG2E * x)) - 1.0f;
}

__device__ __forceinline__ uint32_t s2u(const void* p) {
    uint32_t a;
    asm("{ .reg .u64 t; cvta.to.shared.u64 t, %1; cvt.u32.u64 %0, t; }"
        : "=r"(a) : "l"(p));
    return a;
}
#define MBINIT(a, c) \
    asm volatile("mbarrier.init.shared.b64 [%0], %1;" :: "r"(a), "r"(c) : "memory")
#define MBEXPECT(a, n) \
    asm volatile("mbarrier.arrive.expect_tx.shared.b64 _, [%0], %1;" :: "r"(a), "r"(n) : "memory")
#define BULKCP(dst, src, n, mb) \
    asm volatile("cp.async.bulk.shared::cta.global.mbarrier::complete_tx::bytes [%0], [%1], %2, [%3];" \
                 :: "r"(dst), "l"(src), "r"(n), "r"(mb) : "memory")
__device__ __forceinline__ void mbwait(uint32_t mb, uint32_t parity) {
    uint32_t done;
    asm volatile(
        "{\n\t.reg .pred p;\n\t"
        "mbarrier.try_wait.parity.acquire.cta.shared::cta.b64 p, [%1], %2;\n\t"
        "selp.b32 %0, 1, 0, p;\n\t}"
        : "=r"(done) : "r"(mb), "r"(parity) : "memory");
    if (!done) {
        asm volatile(
            "{\n\t.reg .pred P1;\n\t"
            "W_%=:\n\t"
            "mbarrier.try_wait.parity.acquire.cta.shared::cta.b64 P1, [%0], %1, 0x989680;\n\t"
            "@P1 bra.uni D_%=;\n\t"
            "bra.uni W_%=;\n\t"
            "D_%=:\n\t}"
            :: "r"(mb), "r"(parity) : "memory");
    }
}

// ============================================================================
// Kernel 1: gx[t][b][g] = b_ih0[g] + b_hh0[g] + x[b,t,:] . w_ih0[g,:]
// ============================================================================
#define TT 128
__global__ __launch_bounds__(256, 4)
void xgate_kernel(const float* __restrict__ x,
                  const float* __restrict__ w_ih0,
                  const float* __restrict__ b_ih0,
                  const float* __restrict__ b_hh0) {
    __shared__ __align__(16) float xs[TT][I_];   // 8 KB
    const int b   = blockIdx.y;
    const int t0  = blockIdx.x * TT;
    const int tid = threadIdx.x;

    const float4* src = (const float4*)(x + ((size_t)b * T_ + t0) * I_);
    ((float4*)xs)[tid]       = src[tid];
    ((float4*)xs)[tid + 256] = src[tid + 256];
    __syncthreads();

    if (tid < G_) {
        ull w[8];
        #pragma unroll
        for (int k2 = 0; k2 < 8; k2++)
            w[k2] = pk2(__ldg(&w_ih0[tid * I_ + 2 * k2]),
                        __ldg(&w_ih0[tid * I_ + 2 * k2 + 1]));
        const float bias = __ldg(&b_ih0[tid]) + __ldg(&b_hh0[tid]);
        for (int tt = 0; tt < TT; tt++) {
            ull acc = pk2(bias, 0.0f);
            #pragma unroll
            for (int q = 0; q < 4; q++) {
                const ulonglong2 v = *(const ulonglong2*)&xs[tt][4 * q];
                fma2(acc, w[2 * q],     v.x);
                fma2(acc, w[2 * q + 1], v.y);
            }
            g_gx[((size_t)(t0 + tt) * B_ + b) * G_ + tid] = rsum(acc);
        }
    }
}

// ============================================================================
// Kernel 2: fused 2-layer LSTM recurrence + FC head.
// iter it: L1 step it (gx[it], h1_{it-1});  L2 step it-1 (h1_{it-1}, h2_{it-2})
// 3 gate groups of 7 warps: G0: gx + h1.Whh0 ; G1: h1.Wih1 ; G2: h2.Whh1.
// Gate loop: rows in pairs, rolling depth-1 prefetch of next q-chunk so every
// LDS has >=4 issue slots before its consuming FFMA2; 4 independent FMA chains.
// ============================================================================
__global__ __launch_bounds__(NTH, 1)
void fused_lstm_kernel(const float* __restrict__ w_hh0,  // [G, H]
                       const float* __restrict__ w_ih1,  // [G, H]
                       const float* __restrict__ w_hh1,  // [G, H]
                       const float* __restrict__ b_ih1,
                       const float* __restrict__ b_hh1,
                       const float* __restrict__ fc1_w,  // [FC, H]
                       const float* __restrict__ fc1_b,
                       const float* __restrict__ fc2_w,  // [1, FC]
                       const float* __restrict__ fc2_b,
                       float* __restrict__ out)          // [B, 1]
{
    __shared__ __align__(16) float hx[2][NB][52];   // [0]=h1, [1]=h2 (padded)
    __shared__ __align__(16) float gxs[2][SLAB];    // gx slab double buffer
    __shared__ float gl1[NB][G_];                   // L1 gates (full)
    __shared__ float p1[NB][G_];                    // L2 partial (h1 part)
    __shared__ float p2[NB][G_];                    // L2 partial (h2 part)
    __shared__ __align__(8) ull mbar[2];

    const int tid  = threadIdx.x;
    const int row0 = blockIdx.x * NB;
    const int gidx = tid / 224;            // group 0/1/2
    const int g    = tid - gidx * 224;     // gate index if < 200
    const bool isG = (g < G_);

    const uint32_t mb0 = s2u(&mbar[0]);
    const uint32_t mb1 = s2u(&mbar[1]);
    const uint32_t gx0 = s2u(&gxs[0][0]);
    const uint32_t gx1 = s2u(&gxs[1][0]);

    for (int i = tid; i < 2 * NB * 52; i += NTH) ((float*)hx)[i] = 0.0f;
    if (tid == 0) { MBINIT(mb0, 1); MBINIT(mb1, 1); }
    __syncthreads();

    if (tid == 0) {
        MBEXPECT(mb0, SLAB_BYTES);
        BULKCP(gx0, (const void*)(g_gx + (size_t)row0 * G_), SLAB_BYTES, mb0);
    }

    // ---- weights: one matrix per group, 26 f32x2 chunks each ----
    ull w[26];
    float bias2 = 0.0f;
    if (isG) {
        const float* wm = (gidx == 0) ? w_hh0 : (gidx == 1) ? w_ih1 : w_hh1;
        #pragma unroll
        for (int k2 = 0; k2 < 26; k2++) {
            float a0 = (2 * k2     < H_) ? __ldg(&wm[g * H_ + 2 * k2])     : 0.0f;
            float a1 = (2 * k2 + 1 < H_) ? __ldg(&wm[g * H_ + 2 * k2 + 1]) : 0.0f;
            w[k2] = pk2(a0, a1);
        }
        if (gidx == 1) bias2 = __ldg(&b_ih1[g]) + __ldg(&b_hh1[g]);
    }

    // ---- combine ownership ----
    // k=0: every thread owns cell tid (all < 700).
    // k=1: cells 672..699 owned by tid 644..671 (G2 tail; lightest group).
    float c_st[2] = {0.0f, 0.0f};
    int   coff[2], hoff[2];
    bool  cl2[2];
    const bool has2 = (tid >= 644);
    #pragma unroll
    for (int k = 0; k < 2; k++) {
        const int cell = (k == 0) ? tid : (has2 ? tid + 28 : 0);
        cl2[k] = (cell >= NC1);
        const int rem = cl2[k] ? cell - NC1 : cell;
        const int r = rem / H_;
        const int j = rem - r * H_;
        coff[k] = r * G_ + j;
        hoff[k] = (cl2[k] ? NB * 52 : 0) + r * 52 + j;
    }

    int ph0 = 0, ph1 = 0;
    for (int it = 0; it <= T_; it++) {
        const int buf = it & 1;

        if (tid == 0 && it < T_) {
            const int tn = (it + 1 < T_) ? (it + 1) : (T_ - 1);
            const uint32_t mbn = buf ? mb0 : mb1;
            const uint32_t gxn = buf ? gx0 : gx1;
            MBEXPECT(mbn, SLAB_BYTES);
            BULKCP(gxn, (const void*)(g_gx + ((size_t)tn * B_ + row0) * G_),
                   SLAB_BYTES, mbn);
        }

        // ---- gate phase: row pairs with rolling depth-1 prefetch ----
        if (isG) {
            const int hsel = (gidx == 2) ? 1 : 0;
            if (gidx == 0) {
                mbwait(buf ? mb1 : mb0, buf ? ph1 : ph0);
                if (buf) ph1 ^= 1; else ph0 ^= 1;
            }
            float* dst = (gidx == 0) ? &gl1[0][0] : (gidx == 1) ? &p1[0][0] : &p2[0][0];

            // three row pairs
            #pragma unroll
            for (int rp = 0; rp < 3; rp++) {
                const int rA = 2 * rp, rB = 2 * rp + 1;
                ull aeA, aeB;
                if (gidx == 0) {
                    aeA = pk2(gxs[buf][rA * G_ + g], 0.0f);
                    aeB = pk2(gxs[buf][rB * G_ + g], 0.0f);
                } else if (gidx == 1) {
                    aeA = pk2(bias2, 0.0f);
                    aeB = pk2(bias2, 0.0f);
                } else {
                    aeA = 0ull; aeB = 0ull;
                }
                ull aoA = 0ull, aoB = 0ull;
                ulonglong2 vA = *(const ulonglong2*)&hx[hsel][rA][0];
                ulonglong2 vB = *(const ulonglong2*)&hx[hsel][rB][0];
                #pragma unroll
                for (int q = 0; q < 13; q++) {
                    ulonglong2 vA1, vB1;
                    if (q < 12) {
                        vA1 = *(const ulonglong2*)&hx[hsel][rA][4 * (q + 1)];
                        vB1 = *(const ulonglong2*)&hx[hsel][rB][4 * (q + 1)];
                    }
                    fma2(aeA, w[2 * q],     vA.x);
                    fma2(aoA, w[2 * q + 1], vA.y);
                    fma2(aeB, w[2 * q],     vB.x);
                    fma2(aoB, w[2 * q + 1], vB.y);
                    if (q < 12) { vA = vA1; vB = vB1; }
                }
                dst[rA * G_ + g] = rsum(aeA) + rsum(aoA);
                dst[rB * G_ + g] = rsum(aeB) + rsum(aoB);
            }
            // last row (r = 6), single with rolling prefetch
            {
                const int r = 6;
                ull ae;
                if (gidx == 0)      ae = pk2(gxs[buf][r * G_ + g], 0.0f);
                else if (gidx == 1) ae = pk2(bias2, 0.0f);
                else                ae = 0ull;
                ull ao = 0ull;
                ulonglong2 v = *(const ulonglong2*)&hx[hsel][r][0];
                #pragma unroll
                for (int q = 0; q < 13; q++) {
                    ulonglong2 v1;
                    if (q < 12) v1 = *(const ulonglong2*)&hx[hsel][r][4 * (q + 1)];
                    fma2(ae, w[2 * q],     v.x);
                    fma2(ao, w[2 * q + 1], v.y);
                    if (q < 12) v = v1;
                }
                dst[r * G_ + g] = rsum(ae) + rsum(ao);
            }
        }
        __syncthreads();

        // ---- combine: 1-2 cells per thread (gate order i, f, g, o) ----
        #pragma unroll
        for (int k = 0; k < 2; k++) {
            const bool own = (k == 0) || has2;
            if (own) {
                const bool act = cl2[k] ? (it >= 1) : (it < T_);
                if (act) {
                    const int o = coff[k];
                    float gi, gf, gg, go;
                    if (cl2[k]) {
                        const float* q1 = &p1[0][0];
                        const float* q2 = &p2[0][0];
                        gi = q1[o]           + q2[o];
                        gf = q1[o + H_]      + q2[o + H_];
                        gg = q1[o + 2 * H_]  + q2[o + 2 * H_];
                        go = q1[o + 3 * H_]  + q2[o + 3 * H_];
                    } else {
                        const float* q0 = &gl1[0][0];
                        gi = q0[o];
                        gf = q0[o + H_];
                        gg = q0[o + 2 * H_];
                        go = q0[o + 3 * H_];
                    }
                    const float ig = sigf(gi);
                    const float fg = sigf(gf);
                    const float gv = tanh_f(gg);
                    const float og = sigf(go);
                    c_st[k] = fg * c_st[k] + ig * gv;
                    ((float*)hx)[hoff[k]] = og * tanh_f(c_st[k]);
                }
            }
        }
        __syncthreads();
    }

    // ---- FC head: warps 0-6 each handle one batch row, shfl reduction ----
    const int wid  = tid / 32;
    const int lane = tid - wid * 32;
    if (wid < NB) {
        const int row = row0 + wid;
        if (row < B_) {
            float s = 0.0f;
            #pragma unroll
            for (int uu = 0; uu < 2; uu++) {
                const int u = lane + uu * 32;
                float a = __ldg(&fc1_b[u]);
                #pragma unroll
                for (int k = 0; k < H_; k++)
                    a += __ldg(&fc1_w[u * H_ + k]) * hx[1][wid][k];
                a = fmaxf(a, 0.0f);
                s += a * __ldg(&fc2_w[u]);
            }
            #pragma unroll
            for (int off = 16; off > 0; off >>= 1)
                s += __shfl_down_sync(0xffffffffu, s, off);
            if (lane == 0) out[row] = s + __ldg(&fc2_b[0]);
        }
    }
}

extern "C" void kernel_launch(void* const* d_in, const int* in_sizes, int n_in,
                              void* d_out, int out_size) {
    const float* x     = (const float*)d_in[0];
    const float* w_ih0 = (const float*)d_in[1];
    const float* w_hh0 = (const float*)d_in[2];
    const float* b_ih0 = (const float*)d_in[3];
    const float* b_hh0 = (const float*)d_in[4];
    const float* w_ih1 = (const float*)d_in[5];
    const float* w_hh1 = (const float*)d_in[6];
    const float* b_ih1 = (const float*)d_in[7];
    const float* b_hh1 = (const float*)d_in[8];
    const float* fc1_w = (const float*)d_in[9];
    const float* fc1_b = (const float*)d_in[10];
    const float* fc2_w = (const float*)d_in[11];
    const float* fc2_b = (const float*)d_in[12];
    float* out = (float*)d_out;

    dim3 xg_grid(T_ / TT, B_);
    xgate_kernel<<<xg_grid, 256>>>(x, w_ih0, b_ih0, b_hh0);

    const int grid = (B_ + NB - 1) / NB;   // 147
    fused_lstm_kernel<<<grid, NTH>>>(
        w_hh0, w_ih1, w_hh1, b_ih1, b_hh1,
        fc1_w, fc1_b, fc2_w, fc2_b, out);
}